// round 1
// baseline (speedup 1.0000x reference)
#include <cuda_runtime.h>
#include <math.h>

#define T_TOK   4096
#define D_MODEL 2048
#define FF      8192
#define NE      8
#define MAX_MT  32           // ceil(T_TOK / 128)

// ---------------- scratch (no cudaMalloc allowed) ----------------
__device__ int   g_idx[T_TOK];
__device__ float g_w[T_TOK];
__device__ int   g_order[T_TOK];
__device__ int   g_off[NE + 1];
__device__ float g_H[(size_t)T_TOK * FF];   // 128 MB fp32 scratch, permuted-row order

// ---------------- router: logits -> (argmax idx, max softmax prob) ----------------
__global__ void router_kernel(const float* __restrict__ x, const float* __restrict__ Wr) {
    __shared__ float sx[D_MODEL];
    __shared__ float slog[NE];
    const int t   = blockIdx.x;
    const int tid = threadIdx.x;             // 256 threads = 8 warps
    const float* xr = x + (size_t)t * D_MODEL;
    for (int i = tid * 4; i < D_MODEL; i += 256 * 4)
        *(float4*)(sx + i) = *(const float4*)(xr + i);
    __syncthreads();

    const int w = tid >> 5, lane = tid & 31;
    const float* wr = Wr + (size_t)w * D_MODEL;
    float s = 0.f;
    for (int i = lane; i < D_MODEL; i += 32) s += sx[i] * wr[i];
    #pragma unroll
    for (int o = 16; o; o >>= 1) s += __shfl_xor_sync(0xffffffffu, s, o);
    if (lane == 0) slog[w] = s;
    __syncthreads();

    if (tid == 0) {
        float mx = slog[0]; int mi = 0;
        #pragma unroll
        for (int e = 1; e < NE; e++) if (slog[e] > mx) { mx = slog[e]; mi = e; }  // first-max ties
        float sum = 0.f;
        #pragma unroll
        for (int e = 0; e < NE; e++) sum += expf(slog[e] - mx);
        g_idx[t] = mi;
        g_w[t]   = 1.0f / sum;               // = max softmax prob
    }
}

// ---------------- bucket tokens by expert (single block; re-runs cleanly per replay) -------
__global__ void bucket_kernel() {
    __shared__ int cnt[NE];
    __shared__ int off[NE];
    const int tid = threadIdx.x;
    if (tid < NE) cnt[tid] = 0;
    __syncthreads();
    for (int t = tid; t < T_TOK; t += blockDim.x) atomicAdd(&cnt[g_idx[t]], 1);
    __syncthreads();
    if (tid == 0) {
        int acc = 0;
        #pragma unroll
        for (int e = 0; e < NE; e++) { off[e] = acc; g_off[e] = acc; acc += cnt[e]; }
        g_off[NE] = acc;
    }
    __syncthreads();
    for (int t = tid; t < T_TOK; t += blockDim.x) {
        int p = atomicAdd(&off[g_idx[t]], 1);
        g_order[p] = t;
    }
}

__device__ __forceinline__ float gelu_exact(float v) {
    return 0.5f * v * (1.0f + erff(v * 0.70710678118654752440f));
}

// ---------------- GEMM1: H[p, f] = gelu( x[tok(p), :] @ W1[e] ), gathered rows ----------------
// tile: BM=128, BN=128, BK=8, 256 threads, 8x8 per-thread, double-buffered smem.
__global__ void __launch_bounds__(256)
gemm1_kernel(const float* __restrict__ x, const float* __restrict__ W1) {
    const int e    = blockIdx.y >> 5;
    const int mt   = blockIdx.y & 31;
    const int base = g_off[e];
    const int cnt  = g_off[e + 1] - base;
    const int row0 = mt * 128;
    if (row0 >= cnt) return;

    __shared__ float As[2][8][128];
    __shared__ float Bs[2][8][128];
    __shared__ int   s_tok[128];

    const int tid = threadIdx.x;
    if (tid < 128) {
        int r = row0 + tid;
        s_tok[tid] = (r < cnt) ? g_order[base + r] : -1;
    }
    __syncthreads();

    const int n0 = blockIdx.x * 128;
    const float* W1p = W1 + (size_t)e * D_MODEL * FF;

    const int arow = tid >> 1,  ac = (tid & 1) * 4;
    const int brow = tid >> 5,  bc = (tid & 31) * 4;
    const int tok  = s_tok[arow];
    const float* aptr = (tok >= 0) ? (x + (size_t)tok * D_MODEL + ac) : x;  // guarded below
    const float* bptr = W1p + (size_t)brow * FF + n0 + bc;

    float4 ra = (tok >= 0) ? *(const float4*)aptr : make_float4(0.f, 0.f, 0.f, 0.f);
    float4 rb = *(const float4*)bptr;
    As[0][ac + 0][arow] = ra.x; As[0][ac + 1][arow] = ra.y;
    As[0][ac + 2][arow] = ra.z; As[0][ac + 3][arow] = ra.w;
    *(float4*)&Bs[0][brow][bc] = rb;
    __syncthreads();

    float acc[8][8] = {};
    const int tx = tid & 15, ty = tid >> 4;
    int cur = 0;

    for (int k0 = 0; k0 < D_MODEL; k0 += 8) {
        const int nxt = k0 + 8;
        if (nxt < D_MODEL) {
            ra = (tok >= 0) ? *(const float4*)(aptr + nxt) : make_float4(0.f, 0.f, 0.f, 0.f);
            rb = *(const float4*)(bptr + (size_t)nxt * FF);
        }
        #pragma unroll
        for (int k = 0; k < 8; k++) {
            float4 a0 = *(float4*)&As[cur][k][ty * 8];
            float4 a1 = *(float4*)&As[cur][k][ty * 8 + 4];
            float4 b0 = *(float4*)&Bs[cur][k][tx * 8];
            float4 b1 = *(float4*)&Bs[cur][k][tx * 8 + 4];
            float av[8] = {a0.x, a0.y, a0.z, a0.w, a1.x, a1.y, a1.z, a1.w};
            float bv[8] = {b0.x, b0.y, b0.z, b0.w, b1.x, b1.y, b1.z, b1.w};
            #pragma unroll
            for (int i = 0; i < 8; i++)
                #pragma unroll
                for (int j = 0; j < 8; j++)
                    acc[i][j] = fmaf(av[i], bv[j], acc[i][j]);
        }
        if (nxt < D_MODEL) {
            const int nb = cur ^ 1;
            As[nb][ac + 0][arow] = ra.x; As[nb][ac + 1][arow] = ra.y;
            As[nb][ac + 2][arow] = ra.z; As[nb][ac + 3][arow] = ra.w;
            *(float4*)&Bs[nb][brow][bc] = rb;
            __syncthreads();
            cur = nb;
        }
    }

    #pragma unroll
    for (int i = 0; i < 8; i++) {
        const int row = ty * 8 + i;
        if (s_tok[row] >= 0) {
            float* hp = g_H + (size_t)(base + row0 + row) * FF + n0 + tx * 8;
            float4 o0, o1;
            o0.x = gelu_exact(acc[i][0]); o0.y = gelu_exact(acc[i][1]);
            o0.z = gelu_exact(acc[i][2]); o0.w = gelu_exact(acc[i][3]);
            o1.x = gelu_exact(acc[i][4]); o1.y = gelu_exact(acc[i][5]);
            o1.z = gelu_exact(acc[i][6]); o1.w = gelu_exact(acc[i][7]);
            *(float4*)hp       = o0;
            *(float4*)(hp + 4) = o1;
        }
    }
}

// ---------------- GEMM2: out[tok, d] = w[tok] * ( H[p, :] @ W2[e] ) ----------------
__global__ void __launch_bounds__(256)
gemm2_kernel(const float* __restrict__ W2, float* __restrict__ out) {
    const int e    = blockIdx.y >> 5;
    const int mt   = blockIdx.y & 31;
    const int base = g_off[e];
    const int cnt  = g_off[e + 1] - base;
    const int row0 = mt * 128;
    if (row0 >= cnt) return;

    __shared__ float As[2][8][128];
    __shared__ float Bs[2][8][128];
    __shared__ int   s_tok[128];
    __shared__ float s_wv[128];

    const int tid = threadIdx.x;
    if (tid < 128) {
        int r = row0 + tid;
        if (r < cnt) {
            int tk = g_order[base + r];
            s_tok[tid] = tk;
            s_wv[tid]  = g_w[tk];
        } else {
            s_tok[tid] = -1;
            s_wv[tid]  = 0.f;
        }
    }
    __syncthreads();

    const int n0 = blockIdx.x * 128;
    const float* W2p = W2 + (size_t)e * FF * D_MODEL;

    const int arow = tid >> 1,  ac = (tid & 1) * 4;
    const int brow = tid >> 5,  bc = (tid & 31) * 4;
    const bool avalid = (row0 + arow) < cnt;
    const float* aptr = g_H + (size_t)(base + row0 + (avalid ? arow : 0)) * FF + ac;
    const float* bptr = W2p + (size_t)brow * D_MODEL + n0 + bc;

    float4 ra = avalid ? *(const float4*)aptr : make_float4(0.f, 0.f, 0.f, 0.f);
    float4 rb = *(const float4*)bptr;
    As[0][ac + 0][arow] = ra.x; As[0][ac + 1][arow] = ra.y;
    As[0][ac + 2][arow] = ra.z; As[0][ac + 3][arow] = ra.w;
    *(float4*)&Bs[0][brow][bc] = rb;
    __syncthreads();

    float acc[8][8] = {};
    const int tx = tid & 15, ty = tid >> 4;
    int cur = 0;

    for (int k0 = 0; k0 < FF; k0 += 8) {
        const int nxt = k0 + 8;
        if (nxt < FF) {
            ra = avalid ? *(const float4*)(aptr + nxt) : make_float4(0.f, 0.f, 0.f, 0.f);
            rb = *(const float4*)(bptr + (size_t)nxt * D_MODEL);
        }
        #pragma unroll
        for (int k = 0; k < 8; k++) {
            float4 a0 = *(float4*)&As[cur][k][ty * 8];
            float4 a1 = *(float4*)&As[cur][k][ty * 8 + 4];
            float4 b0 = *(float4*)&Bs[cur][k][tx * 8];
            float4 b1 = *(float4*)&Bs[cur][k][tx * 8 + 4];
            float av[8] = {a0.x, a0.y, a0.z, a0.w, a1.x, a1.y, a1.z, a1.w};
            float bv[8] = {b0.x, b0.y, b0.z, b0.w, b1.x, b1.y, b1.z, b1.w};
            #pragma unroll
            for (int i = 0; i < 8; i++)
                #pragma unroll
                for (int j = 0; j < 8; j++)
                    acc[i][j] = fmaf(av[i], bv[j], acc[i][j]);
        }
        if (nxt < FF) {
            const int nb = cur ^ 1;
            As[nb][ac + 0][arow] = ra.x; As[nb][ac + 1][arow] = ra.y;
            As[nb][ac + 2][arow] = ra.z; As[nb][ac + 3][arow] = ra.w;
            *(float4*)&Bs[nb][brow][bc] = rb;
            __syncthreads();
            cur = nb;
        }
    }

    #pragma unroll
    for (int i = 0; i < 8; i++) {
        const int row = ty * 8 + i;
        const int tk  = s_tok[row];
        if (tk >= 0) {
            const float wv = s_wv[row];
            float* op = out + (size_t)tk * D_MODEL + n0 + tx * 8;
            float4 o0, o1;
            o0.x = acc[i][0] * wv; o0.y = acc[i][1] * wv;
            o0.z = acc[i][2] * wv; o0.w = acc[i][3] * wv;
            o1.x = acc[i][4] * wv; o1.y = acc[i][5] * wv;
            o1.z = acc[i][6] * wv; o1.w = acc[i][7] * wv;
            *(float4*)op       = o0;
            *(float4*)(op + 4) = o1;
        }
    }
}

// ---------------- launch ----------------
extern "C" void kernel_launch(void* const* d_in, const int* in_sizes, int n_in,
                              void* d_out, int out_size) {
    const float* x  = (const float*)d_in[0];
    const float* Wr = (const float*)d_in[1];
    const float* W1 = (const float*)d_in[2];
    const float* W2 = (const float*)d_in[3];
    float* out = (float*)d_out;

    router_kernel<<<T_TOK, 256>>>(x, Wr);
    bucket_kernel<<<1, 1024>>>();
    gemm1_kernel<<<dim3(FF / 128,      NE * MAX_MT), 256>>>(x, W1);
    gemm2_kernel<<<dim3(D_MODEL / 128, NE * MAX_MT), 256>>>(W2, out);
}

// round 3
// speedup vs baseline: 3.2578x; 3.2578x over previous
#include <cuda_runtime.h>
#include <cuda_bf16.h>
#include <math.h>
#include <stdint.h>

#define T_TOK   4096
#define D_MODEL 2048
#define FF      8192
#define NE      8
#define PM      40          // padded m-tiles: 4096/128 + 8 pad tiles
#define KT1     32          // GEMM1 k-tiles (D/64)
#define NT1     64          // GEMM1 n-tiles (FF/128)
#define KT2     128         // GEMM2 k-tiles (FF/64)
#define NT2     16          // GEMM2 n-tiles (D/128)
#define BLKB    32768       // one (hi,lo) operand block pair: 2 x 128rows x 128B

// ---------------- scratch (__device__ globals; no cudaMalloc) ----------------
__device__ int   g_idx[T_TOK];
__device__ float g_w[T_TOK];
__device__ int   g_order[T_TOK];
__device__ int   g_off[NE + 1];
__device__ int   g_poff[NE + 1];
__device__ int   g_ptok[PM * 128];

__device__ __align__(128) char g_A [(size_t)PM * KT1 * BLKB];          //  42 MB
__device__ __align__(128) char g_B1[(size_t)NE * NT1 * KT1 * BLKB];    // 537 MB
__device__ __align__(128) char g_B2[(size_t)NE * NT2 * KT2 * BLKB];    // 537 MB
__device__ __align__(128) char g_H [(size_t)PM * KT2 * BLKB];          // 168 MB

// ---------------- helpers ----------------
__device__ __forceinline__ uint32_t s2u(const void* p) {
    uint32_t a;
    asm("{ .reg .u64 t; cvta.to.shared.u64 t, %1; cvt.u32.u64 %0, t; }" : "=r"(a) : "l"(p));
    return a;
}
__device__ __forceinline__ uint32_t pack2(float a, float b) {
    __nv_bfloat162 t = __floats2bfloat162_rn(a, b);
    return *(uint32_t*)&t;
}
__device__ __forceinline__ void split1(float v, float& hi, float& lo) {
    __nv_bfloat16 h = __float2bfloat16_rn(v);
    hi = __bfloat162float(h);
    lo = v - hi;
}
__device__ __forceinline__ float gelu_exact(float v) {
    return 0.5f * v * (1.0f + erff(v * 0.70710678118654752440f));
}
__device__ __forceinline__ void mbar_init(uint32_t m, uint32_t c) {
    asm volatile("mbarrier.init.shared::cta.b64 [%0], %1;" :: "r"(m), "r"(c) : "memory");
}
__device__ __forceinline__ void mbar_arrive(uint32_t m) {
    asm volatile("mbarrier.arrive.shared::cta.b64 _, [%0];" :: "r"(m) : "memory");
}
__device__ __forceinline__ void mbar_expect_tx(uint32_t m, uint32_t b) {
    asm volatile("mbarrier.arrive.expect_tx.shared::cta.b64 _, [%0], %1;"
                 :: "r"(m), "r"(b) : "memory");
}
__device__ __forceinline__ void mbar_wait(uint32_t m, uint32_t ph) {
    asm volatile(
        "{\n\t.reg .pred P;\n"
        "W_%=:\n\t"
        "mbarrier.try_wait.parity.acquire.cta.shared::cta.b64 P, [%0], %1, 0x989680;\n\t"
        "@P bra.uni D_%=;\n\t"
        "bra.uni W_%=;\n"
        "D_%=:\n\t}"
        :: "r"(m), "r"(ph) : "memory");
}
__device__ __forceinline__ void bulk_g2s(uint32_t dst, const void* src, uint32_t bytes,
                                         uint32_t mbar) {
    asm volatile(
        "cp.async.bulk.shared::cta.global.mbarrier::complete_tx::bytes [%0], [%1], %2, [%3];"
        :: "r"(dst), "l"(src), "r"(bytes), "r"(mbar) : "memory");
}
__device__ __forceinline__ void ldsm4(uint32_t& r0, uint32_t& r1, uint32_t& r2, uint32_t& r3,
                                      uint32_t a) {
    asm volatile("ldmatrix.sync.aligned.m8n8.x4.shared.b16 {%0,%1,%2,%3}, [%4];"
                 : "=r"(r0), "=r"(r1), "=r"(r2), "=r"(r3) : "r"(a));
}
__device__ __forceinline__ void mma_bf16(float* d, const uint32_t* a, const uint32_t* b) {
    asm volatile(
        "mma.sync.aligned.m16n8k16.row.col.f32.bf16.bf16.f32 "
        "{%0,%1,%2,%3}, {%4,%5,%6,%7}, {%8,%9}, {%0,%1,%2,%3};"
        : "+f"(d[0]), "+f"(d[1]), "+f"(d[2]), "+f"(d[3])
        : "r"(a[0]), "r"(a[1]), "r"(a[2]), "r"(a[3]), "r"(b[0]), "r"(b[1]));
}

// ---------------- router ----------------
__global__ void router_kernel(const float* __restrict__ x, const float* __restrict__ Wr) {
    __shared__ float sx[D_MODEL];
    __shared__ float slog[NE];
    const int t = blockIdx.x, tid = threadIdx.x;
    const float* xr = x + (size_t)t * D_MODEL;
    for (int i = tid * 4; i < D_MODEL; i += 256 * 4)
        *(float4*)(sx + i) = *(const float4*)(xr + i);
    __syncthreads();
    const int w = tid >> 5, lane = tid & 31;
    const float* wr = Wr + (size_t)w * D_MODEL;
    float s = 0.f;
    for (int i = lane; i < D_MODEL; i += 32) s += sx[i] * wr[i];
    #pragma unroll
    for (int o = 16; o; o >>= 1) s += __shfl_xor_sync(0xffffffffu, s, o);
    if (lane == 0) slog[w] = s;
    __syncthreads();
    if (tid == 0) {
        float mx = slog[0]; int mi = 0;
        #pragma unroll
        for (int e = 1; e < NE; e++) if (slog[e] > mx) { mx = slog[e]; mi = e; }
        float sum = 0.f;
        #pragma unroll
        for (int e = 0; e < NE; e++) sum += expf(slog[e] - mx);
        g_idx[t] = mi;
        g_w[t] = 1.0f / sum;
    }
}

// ---------------- bucket + padded offsets + padded-row token map ----------------
__global__ void bucket_kernel() {
    __shared__ int cnt[NE], off[NE], soff[NE], spo[NE + 1];
    const int tid = threadIdx.x;
    if (tid < NE) cnt[tid] = 0;
    __syncthreads();
    for (int t = tid; t < T_TOK; t += blockDim.x) atomicAdd(&cnt[g_idx[t]], 1);
    __syncthreads();
    if (tid == 0) {
        int acc = 0, pacc = 0;
        #pragma unroll
        for (int e = 0; e < NE; e++) {
            off[e] = acc; soff[e] = acc; g_off[e] = acc;
            spo[e] = pacc; g_poff[e] = pacc;
            acc += cnt[e];
            pacc += (cnt[e] + 127) & ~127;
        }
        g_off[NE] = acc;
        spo[NE] = pacc; g_poff[NE] = pacc;
    }
    __syncthreads();
    for (int t = tid; t < T_TOK; t += blockDim.x) {
        int p = atomicAdd(&off[g_idx[t]], 1);
        g_order[p] = t;
    }
    __syncthreads();
    for (int p = tid; p < PM * 128; p += blockDim.x) {
        int tk = -1;
        #pragma unroll
        for (int e = 0; e < NE; e++)
            if (p >= spo[e] && p < spo[e] + cnt[e])
                tk = g_order[soff[e] + (p - spo[e])];
        g_ptok[p] = tk;
    }
}

// ---------------- prepass: gather x rows -> swizzled bf16 hi/lo blocks ----------------
__global__ void __launch_bounds__(256) gather_a_kernel(const float* __restrict__ x) {
    const int gt = blockIdx.x, kt = blockIdx.y;
    const int tid = threadIdx.x;
    const int r = tid >> 1, half = tid & 1;
    const int tok = g_ptok[gt * 128 + r];
    uint32_t hw[16], lw[16];
    if (tok >= 0) {
        const float4* src = (const float4*)(x + (size_t)tok * D_MODEL + kt * 64 + half * 32);
        #pragma unroll
        for (int q = 0; q < 8; q++) {
            float4 v = src[q];
            float h0, l0, h1, l1, h2, l2, h3, l3;
            split1(v.x, h0, l0); split1(v.y, h1, l1);
            split1(v.z, h2, l2); split1(v.w, h3, l3);
            hw[q * 2]     = pack2(h0, h1); hw[q * 2 + 1] = pack2(h2, h3);
            lw[q * 2]     = pack2(l0, l1); lw[q * 2 + 1] = pack2(l2, l3);
        }
    } else {
        #pragma unroll
        for (int q = 0; q < 16; q++) { hw[q] = 0; lw[q] = 0; }
    }
    char* blk = g_A + ((size_t)gt * KT1 + kt) * BLKB;
    #pragma unroll
    for (int c = 0; c < 4; c++) {
        int ch = half * 4 + c;
        uint32_t off = (uint32_t)(r * 128) + (uint32_t)((ch ^ (r & 7)) << 4);
        *(uint4*)(blk + off)         = ((uint4*)hw)[c];
        *(uint4*)(blk + 16384 + off) = ((uint4*)lw)[c];
    }
}

// ---------------- prepass: transpose + convert weights -> swizzled blocks ----------------
// W=1: src [E][D][F] -> g_B1 blocks (e, nt over F, kt over D)
// W=2: src [E][F][D] -> g_B2 blocks (e, nt over D, kt over F)
template <int W>
__global__ void __launch_bounds__(256) transconv_kernel(const float* __restrict__ src) {
    constexpr int Cn = (W == 1) ? FF : D_MODEL;
    constexpr int Rk = (W == 1) ? D_MODEL : FF;
    constexpr int NT = (W == 1) ? NT1 : NT2;
    constexpr int KT = (W == 1) ? KT1 : KT2;
    __shared__ float s[64 * 132];
    const int nt = blockIdx.x, kt = blockIdx.y, e = blockIdx.z;
    const int tid = threadIdx.x;
    const float* sp = src + (size_t)e * Rk * Cn + (size_t)(kt * 64) * Cn + nt * 128;
    #pragma unroll
    for (int i = 0; i < 8; i++) {
        int q = i * 256 + tid;
        int k = q >> 5, c4 = q & 31;
        *(float4*)(s + k * 132 + c4 * 4) = *(const float4*)(sp + (size_t)k * Cn + c4 * 4);
    }
    __syncthreads();
    const int n = tid >> 1, half = tid & 1;
    uint32_t hw[16], lw[16];
    #pragma unroll
    for (int jw = 0; jw < 16; jw++) {
        float v0 = s[(half * 32 + jw * 2) * 132 + n];
        float v1 = s[(half * 32 + jw * 2 + 1) * 132 + n];
        float h0, l0, h1, l1;
        split1(v0, h0, l0); split1(v1, h1, l1);
        hw[jw] = pack2(h0, h1);
        lw[jw] = pack2(l0, l1);
    }
    char* dst = ((W == 1) ? g_B1 : g_B2) + (((size_t)e * NT + nt) * KT + kt) * BLKB;
    #pragma unroll
    for (int c = 0; c < 4; c++) {
        int ch = half * 4 + c;
        uint32_t off = (uint32_t)(n * 128) + (uint32_t)((ch ^ (n & 7)) << 4);
        *(uint4*)(dst + off)         = ((uint4*)hw)[c];
        *(uint4*)(dst + 16384 + off) = ((uint4*)lw)[c];
    }
}

// ---------------- warp-MMA grouped GEMM, bulk-copy 3-stage pipeline ----------------
// smem: 3 stages x 64KB (A hi/lo 32KB | B hi/lo 32KB) + s_tok + s_wv + mbarriers
#define ST_BYTES   65536u
#define SM_TOKOFF  196608
#define SM_WVOFF   197120
#define SM_MBROFF  197632
#define SMEM_TOT   197696

template <int PHASE>
__global__ void __launch_bounds__(288, 1) moe_gemm(float* __restrict__ out) {
    constexpr int KT = (PHASE == 1) ? KT1 : KT2;
    const int e = blockIdx.y >> 5, mt = blockIdx.y & 31;
    const int cnt = g_off[e + 1] - g_off[e];
    if (mt >= ((cnt + 127) >> 7)) return;
    const int gt = (g_poff[e] >> 7) + mt;
    const int nt = blockIdx.x;

    extern __shared__ char smem[];
    const uint32_t sb = s2u(smem);
    int* s_tok = (int*)(smem + SM_TOKOFF);
    float* s_wv = (float*)(smem + SM_WVOFF);
    const uint32_t mfull = sb + SM_MBROFF;       // 3 x 8B
    const uint32_t mempty = sb + SM_MBROFF + 24; // 3 x 8B

    const int tid = threadIdx.x;
    const int wid = tid >> 5, lane = tid & 31;

    if (tid < 128) {
        int tk = g_ptok[gt * 128 + tid];
        s_tok[tid] = tk;
        s_wv[tid] = (tk >= 0) ? g_w[tk] : 0.f;
    }
    if (tid == 0) {
        #pragma unroll
        for (int i = 0; i < 3; i++) { mbar_init(mfull + i * 8, 1); mbar_init(mempty + i * 8, 8); }
    }
    __syncthreads();

    if (wid == 8) {
        // ---------------- producer warp ----------------
        if (lane == 0) {
            const char* srcA = (PHASE == 1) ? (g_A + (size_t)gt * KT1 * BLKB)
                                            : (g_H + (size_t)gt * KT2 * BLKB);
            const char* srcB = (PHASE == 1)
                ? (g_B1 + ((size_t)(e * NT1 + nt)) * KT1 * BLKB)
                : (g_B2 + ((size_t)(e * NT2 + nt)) * KT2 * BLKB);
            int s = 0, r = 0;
            for (int kt = 0; kt < KT; kt++) {
                if (r > 0) mbar_wait(mempty + s * 8, (r - 1) & 1);
                mbar_expect_tx(mfull + s * 8, ST_BYTES);
                uint32_t dst = sb + (uint32_t)s * ST_BYTES;
                bulk_g2s(dst,          srcA + (size_t)kt * BLKB, BLKB, mfull + s * 8);
                bulk_g2s(dst + 32768u, srcB + (size_t)kt * BLKB, BLKB, mfull + s * 8);
                if (++s == 3) { s = 0; r++; }
            }
        }
        return;
    }

    // ---------------- consumer warps ----------------
    const int wm = wid >> 2, wn = wid & 3;
    const int lrA = (lane & 7) + ((lane >> 3) & 1) * 8;
    const int cA0 = lane >> 4;
    uint32_t a_off[4]; int a_rs[4];
    #pragma unroll
    for (int mf = 0; mf < 4; mf++) {
        int rr = wm * 64 + mf * 16 + lrA;
        a_off[mf] = (uint32_t)(rr * 128);
        a_rs[mf] = rr & 7;
    }
    const int lrB = (lane & 7) + ((lane >> 4) << 3);
    const int cB0 = (lane >> 3) & 1;
    uint32_t b_off[2]; int b_rs[2];
    #pragma unroll
    for (int p = 0; p < 2; p++) {
        int rr = wn * 32 + p * 16 + lrB;
        b_off[p] = (uint32_t)(rr * 128);
        b_rs[p] = rr & 7;
    }

    float acc[4][4][4];
    #pragma unroll
    for (int i = 0; i < 4; i++)
        #pragma unroll
        for (int j = 0; j < 4; j++)
            #pragma unroll
            for (int q = 0; q < 4; q++) acc[i][j][q] = 0.f;

    int s = 0, r = 0;
    for (int kt = 0; kt < KT; kt++) {
        mbar_wait(mfull + s * 8, r & 1);
        const uint32_t stA = sb + (uint32_t)s * ST_BYTES;
        const uint32_t stB = stA + 32768u;
        #pragma unroll
        for (int ks = 0; ks < 4; ks++) {
            uint32_t ah[16], al[16], bh[8], bl[8];
            const int cA = cA0 + ks * 2;
            #pragma unroll
            for (int mf = 0; mf < 4; mf++) {
                uint32_t o = a_off[mf] + (uint32_t)((cA ^ a_rs[mf]) << 4);
                ldsm4(ah[mf*4], ah[mf*4+1], ah[mf*4+2], ah[mf*4+3], stA + o);
                ldsm4(al[mf*4], al[mf*4+1], al[mf*4+2], al[mf*4+3], stA + 16384u + o);
            }
            const int cB = cB0 + ks * 2;
            #pragma unroll
            for (int p = 0; p < 2; p++) {
                uint32_t o = b_off[p] + (uint32_t)((cB ^ b_rs[p]) << 4);
                ldsm4(bh[p*4], bh[p*4+1], bh[p*4+2], bh[p*4+3], stB + o);
                ldsm4(bl[p*4], bl[p*4+1], bl[p*4+2], bl[p*4+3], stB + 16384u + o);
            }
            #pragma unroll
            for (int mf = 0; mf < 4; mf++)
                #pragma unroll
                for (int nf = 0; nf < 4; nf++) {
                    const uint32_t* bhf = &bh[(nf >> 1) * 4 + (nf & 1) * 2];
                    const uint32_t* blf = &bl[(nf >> 1) * 4 + (nf & 1) * 2];
                    mma_bf16(acc[mf][nf], &ah[mf * 4], bhf);
                    mma_bf16(acc[mf][nf], &al[mf * 4], bhf);
                    mma_bf16(acc[mf][nf], &ah[mf * 4], blf);
                }
        }
        if (lane == 0) mbar_arrive(mempty + s * 8);
        if (++s == 3) { s = 0; r++; }
    }

    // ---------------- epilogue ----------------
    #pragma unroll
    for (int mf = 0; mf < 4; mf++)
        #pragma unroll
        for (int nf = 0; nf < 4; nf++) {
            const float* c = acc[mf][nf];
            const int rbase = wm * 64 + mf * 16 + (lane >> 2);
            const int ncol = nt * 128 + wn * 32 + nf * 8 + (lane & 3) * 2;
            #pragma unroll
            for (int hh = 0; hh < 2; hh++) {
                const int rl = rbase + hh * 8;
                if (PHASE == 1) {
                    if (s_tok[rl] < 0) continue;
                    float v0 = gelu_exact(c[hh * 2]);
                    float v1 = gelu_exact(c[hh * 2 + 1]);
                    float h0, l0, h1, l1;
                    split1(v0, h0, l0); split1(v1, h1, l1);
                    const int kt2 = ncol >> 6, kl = ncol & 63;
                    char* blk = g_H + ((size_t)gt * KT2 + kt2) * BLKB;
                    uint32_t off = (uint32_t)(rl * 128)
                                 + (uint32_t)((((kl >> 3) ^ (rl & 7)) << 4) + (kl & 7) * 2);
                    *(uint32_t*)(blk + off)          = pack2(h0, h1);
                    *(uint32_t*)(blk + 16384u + off) = pack2(l0, l1);
                } else {
                    const int tk = s_tok[rl];
                    if (tk < 0) continue;
                    const float wv = s_wv[rl];
                    float2 o = make_float2(c[hh * 2] * wv, c[hh * 2 + 1] * wv);
                    *(float2*)(out + (size_t)tk * D_MODEL + ncol) = o;
                }
            }
        }
}

// ---------------- launch ----------------
extern "C" void kernel_launch(void* const* d_in, const int* in_sizes, int n_in,
                              void* d_out, int out_size) {
    const float* x  = (const float*)d_in[0];
    const float* Wr = (const float*)d_in[1];
    const float* W1 = (const float*)d_in[2];
    const float* W2 = (const float*)d_in[3];
    float* out = (float*)d_out;

    cudaFuncSetAttribute(moe_gemm<1>, cudaFuncAttributeMaxDynamicSharedMemorySize, SMEM_TOT);
    cudaFuncSetAttribute(moe_gemm<2>, cudaFuncAttributeMaxDynamicSharedMemorySize, SMEM_TOT);

    router_kernel<<<T_TOK, 256>>>(x, Wr);
    bucket_kernel<<<1, 1024>>>();
    gather_a_kernel<<<dim3(PM, KT1), 256>>>(x);
    transconv_kernel<1><<<dim3(NT1, KT1, NE), 256>>>(W1);
    transconv_kernel<2><<<dim3(NT2, KT2, NE), 256>>>(W2);
    moe_gemm<1><<<dim3(NT1, NE * 32), 288, SMEM_TOT>>>(nullptr);
    moe_gemm<2><<<dim3(NT2, NE * 32), 288, SMEM_TOT>>>(out);
}